// round 16
// baseline (speedup 1.0000x reference)
#include <cuda_runtime.h>

// NCC2D: -mean( cross^2 / (I_var*J_var + 1e-5) ), 9x9 zero-padded box sums.
// cross = IJ - I*J/81 ; I_var = I2 - I^2/81 ; J_var = J2 - J^2/81.
//
// R10 base (22x32 blocks, TPB=128, 4 cols/thread, lb(128,5), guard-free
// interior strips) with a restructured emit:
//   - 4 exchange buffers (guard-padded, 40.6KB): ONE __syncthreads per TWO
//     emitted rows (12 bars/block vs 24). WAR-safe: read(k) < bar(k+1) <
//     write(k+2) with 4-buffer rotation.
//   - window reads L/Own/R as 3 unconditional LDS.128 per product (guard
//     zeros at [0] and [TPB+1] kill all edge predicates/selects).
//   - both rows' new+old LDG.128s (8 loads) batched at pair top -> MLP 8.
//   Block partial -> double atomic; last block finalizes + resets.

#define BW   512
#define BH   512
#define NB   32
#define ROWS 24
#define TPB  128
#define STRIPS 22                    // 21 full strips of 24 + one of 8
#define NBLOCKS (STRIPS * NB)        // 704
#define RVW  (BW / 4)                // float4s per row

__device__ double       g_acc;   // zero-init at load; reset by last block
__device__ unsigned int g_cnt;

__global__ __launch_bounds__(TPB, 5) void ncc_main_k(const float* __restrict__ gI,
                                                     const float* __restrict__ gJ,
                                                     float* __restrict__ out) {
    __shared__ float4 sV[4][5][TPB + 2];   // 4 bufs, guard cols at 0, TPB+1
    __shared__ float  wsum[TPB / 32];

    const int t    = threadIdx.x;
    const int lane = t & 31;
    const int r0   = blockIdx.x * ROWS;
    const size_t img = (size_t)blockIdx.y * ((size_t)BH * BW);
    const float4 z = make_float4(0.f, 0.f, 0.f, 0.f);
    const float inv81 = 1.0f / 81.0f;

    const float4* bI = (const float4*)(gI + img) + t;   // stride RVW per row
    const float4* bJ = (const float4*)(gJ + img) + t;

    // Zero the guard columns of all 4 buffers (covered by first emit barrier).
    if (t < 40) {
        int b = t / 10, rem = t % 10, p = rem >> 1;
        sV[b][p][(rem & 1) ? (TPB + 1) : 0] = z;
    }

    float vI[4]  = {0.f, 0.f, 0.f, 0.f};
    float vJ[4]  = {0.f, 0.f, 0.f, 0.f};
    float vI2[4] = {0.f, 0.f, 0.f, 0.f};
    float vJ2[4] = {0.f, 0.f, 0.f, 0.f};
    float vIJ[4] = {0.f, 0.f, 0.f, 0.f};
    float acc = 0.f;

#define VADD(A1, B1)                                                           \
    {                                                                          \
        const float an[4] = {(A1).x, (A1).y, (A1).z, (A1).w};                  \
        const float bn[4] = {(B1).x, (B1).y, (B1).z, (B1).w};                  \
        _Pragma("unroll")                                                      \
        for (int c = 0; c < 4; ++c) {                                          \
            vI[c] += an[c];                                                    \
            vJ[c] += bn[c];                                                    \
            vI2[c] = fmaf(an[c], an[c], vI2[c]);                               \
            vJ2[c] = fmaf(bn[c], bn[c], vJ2[c]);                               \
            vIJ[c] = fmaf(an[c], bn[c], vIJ[c]);                               \
        }                                                                      \
    }

#define VSUB(AO, BO)                                                           \
    {                                                                          \
        const float ap[4] = {(AO).x, (AO).y, (AO).z, (AO).w};                  \
        const float bp[4] = {(BO).x, (BO).y, (BO).z, (BO).w};                  \
        _Pragma("unroll")                                                      \
        for (int c = 0; c < 4; ++c) {                                          \
            vI[c] -= ap[c];                                                    \
            vJ[c] -= bp[c];                                                    \
            vI2[c] = fmaf(-ap[c], ap[c], vI2[c]);                              \
            vJ2[c] = fmaf(-bp[c], bp[c], vJ2[c]);                              \
            vIJ[c] = fmaf(-ap[c], bp[c], vIJ[c]);                              \
        }                                                                      \
    }

// Store current V state to buffer BUF (threads write slot t+1; guards flank).
#define STORE_V(BUF)                                                           \
    {                                                                          \
        sV[BUF][0][t + 1] = make_float4(vI[0],  vI[1],  vI[2],  vI[3]);        \
        sV[BUF][1][t + 1] = make_float4(vJ[0],  vJ[1],  vJ[2],  vJ[3]);        \
        sV[BUF][2][t + 1] = make_float4(vI2[0], vI2[1], vI2[2], vI2[3]);       \
        sV[BUF][3][t + 1] = make_float4(vJ2[0], vJ2[1], vJ2[2], vJ2[3]);       \
        sV[BUF][4][t + 1] = make_float4(vIJ[0], vIJ[1], vIJ[2], vIJ[3]);       \
    }

// 9-tap horizontal window for product P from buffer BUF: 3 plain LDS.128.
#define DO_WIN(BUF, P)                                                         \
    {                                                                          \
        float4 L = sV[BUF][P][t];                                              \
        float4 O = sV[BUF][P][t + 1];                                          \
        float4 R = sV[BUF][P][t + 2];                                          \
        float w = ((L.x + L.y) + (L.z + L.w))                                  \
                + ((O.x + O.y) + (O.z + O.w)) + R.x;                           \
        box[P][0] = w;                                                         \
        box[P][1] = w = w - L.x + R.y;                                         \
        box[P][2] = w = w - L.y + R.z;                                         \
        box[P][3] =     w - L.z + R.w;                                         \
    }

// Window + NCC for one emitted row from buffer BUF (after the barrier).
#define WIN_ROW(BUF)                                                           \
    {                                                                          \
        float box[5][4];                                                       \
        DO_WIN(BUF, 0)                                                         \
        DO_WIN(BUF, 1)                                                         \
        DO_WIN(BUF, 2)                                                         \
        DO_WIN(BUF, 3)                                                         \
        DO_WIN(BUF, 4)                                                         \
        _Pragma("unroll")                                                      \
        for (int c = 0; c < 4; ++c) {                                          \
            float sI = box[0][c], sJ = box[1][c];                              \
            float cross = fmaf(sI * sJ, -inv81, box[4][c]);                    \
            float Iv    = fmaf(sI * sI, -inv81, box[2][c]);                    \
            float Jv    = fmaf(sJ * sJ, -inv81, box[3][c]);                    \
            float den   = fmaf(Iv, Jv, 1e-5f);                                 \
            acc += __fdividef(cross * cross, den);                             \
        }                                                                      \
    }

    if (r0 >= ROWS && r0 + ROWS + 4 <= BH) {
        // ---------- interior strip (20 of 22): zero range checks ----------
        // Warm-up: add rows r0-4 .. r0+3 (all in-range), no subtract, no emit.
#pragma unroll
        for (int it = 0; it < 8; ++it) {
            const int rn = r0 - 4 + it;
            float4 wa = __ldg(bI + (size_t)rn * RVW);
            float4 wb = __ldg(bJ + (size_t)rn * RVW);
            VADD(wa, wb)
        }
        // First emit pair: it=8 (row r0, no subtract) + it=9 (row r0+1).
        {
            float4 a0 = __ldg(bI + (size_t)(r0 + 4) * RVW);
            float4 b0 = __ldg(bJ + (size_t)(r0 + 4) * RVW);
            float4 a1 = __ldg(bI + (size_t)(r0 + 5) * RVW);
            float4 b1 = __ldg(bJ + (size_t)(r0 + 5) * RVW);
            float4 ao = __ldg(bI + (size_t)(r0 - 4) * RVW);
            float4 bo = __ldg(bJ + (size_t)(r0 - 4) * RVW);
            VADD(a0, b0)
            STORE_V(0)
            VADD(a1, b1)
            VSUB(ao, bo)
            STORE_V(1)
            __syncthreads();
            WIN_ROW(0)
            WIN_ROW(1)
        }
        // Steady pairs q=0..10: ingest rows (r0+6+2q, r0+7+2q), emit 2 rows.
#pragma unroll 1
        for (int q = 0; q < (ROWS - 2) / 2; ++q) {
            const int rnA = r0 + 6 + 2 * q;
            const int bufA = (q & 1) ? 0 : 2;      // rotate {2,3},{0,1},...
            // Batch all 8 loads (MLP 8).
            float4 aA = __ldg(bI + (size_t)rnA * RVW);
            float4 bA = __ldg(bJ + (size_t)rnA * RVW);
            float4 oA = __ldg(bI + (size_t)(rnA - 9) * RVW);
            float4 pA = __ldg(bJ + (size_t)(rnA - 9) * RVW);
            float4 aB = __ldg(bI + (size_t)(rnA + 1) * RVW);
            float4 bB = __ldg(bJ + (size_t)(rnA + 1) * RVW);
            float4 oB = __ldg(bI + (size_t)(rnA - 8) * RVW);
            float4 pB = __ldg(bJ + (size_t)(rnA - 8) * RVW);
            VADD(aA, bA)
            VSUB(oA, pA)
            STORE_V(bufA)
            VADD(aB, bB)
            VSUB(oB, pB)
            STORE_V(bufA + 1)
            __syncthreads();
            WIN_ROW(bufA)
            WIN_ROW(bufA + 1)
        }
    } else {
        // ---------- edge strips: guarded loop, 1 row per barrier ----------
        const int rows_eff = min(ROWS, BH - r0);
        const int iters = rows_eff + 8;
#pragma unroll 1
        for (int it = 0; it < iters; ++it) {
            const int rn = r0 - 4 + it;
            const int ro = rn - 9;
            if (rn >= 0 && rn < BH) {
                float4 wa = __ldg(bI + (size_t)rn * RVW);
                float4 wb = __ldg(bJ + (size_t)rn * RVW);
                VADD(wa, wb)
            }
            if (it >= 9 && ro >= 0) {   // only rows actually added earlier
                float4 wa = __ldg(bI + (size_t)ro * RVW);
                float4 wb = __ldg(bJ + (size_t)ro * RVW);
                VSUB(wa, wb)
            }
            if (it >= 8) {
                const int buf = it & 3;             // 4-buffer rotation
                STORE_V(buf)
                __syncthreads();
                WIN_ROW(buf)
            }
        }
    }
#undef DO_WIN
#undef WIN_ROW
#undef STORE_V
#undef VSUB
#undef VADD

    // Block reduction -> global double atomic; last block finalizes + resets.
#pragma unroll
    for (int o = 16; o; o >>= 1) acc += __shfl_xor_sync(0xffffffffu, acc, o);
    if (lane == 0) wsum[t >> 5] = acc;
    __syncthreads();
    if (t == 0) {
        float bs = 0.f;
#pragma unroll
        for (int w = 0; w < TPB / 32; ++w) bs += wsum[w];
        atomicAdd(&g_acc, (double)bs);
        __threadfence();
        unsigned int done = atomicAdd(&g_cnt, 1u);
        if (done == NBLOCKS - 1) {
            __threadfence();
            double v = *((volatile double*)&g_acc);
            out[0] = (float)(-v * (1.0 / (double)((long long)NB * BH * BW)));
            g_acc = 0.0;          // reset for next graph replay
            g_cnt = 0u;
        }
    }
}

extern "C" void kernel_launch(void* const* d_in, const int* in_sizes, int n_in,
                              void* d_out, int out_size) {
    const float* I = (const float*)d_in[0];
    const float* J = (const float*)d_in[1];
    float* out = (float*)d_out;

    dim3 grid(STRIPS, NB);   // (22, 32) = 704 blocks, single wave at 5/SM
    ncc_main_k<<<grid, TPB>>>(I, J, out);
}

// round 17
// speedup vs baseline: 1.1232x; 1.1232x over previous
#include <cuda_runtime.h>

// NCC2D: -mean( cross^2 / (I_var*J_var + 1e-5) ), 9x9 zero-padded box sums.
// cross = IJ - I*J/81 ; I_var = I2 - I^2/81 ; J_var = J2 - J^2/81.
//
// R10 winner structure (bench 30.8us), unchanged loop form, two local deltas:
//   1) ROWS 24->23, STRIPS 23 -> 736 blocks = 4.97 blocks/SM (vs 4.76):
//      fills the 5-blocks/SM residency almost exactly, still single wave.
//   2) guard-padded smem exchange rows (TPB+2, zero guard cols) -> window
//      reads are 3 unconditional LDS.128 per product, no edge selects.
//   Everything else identical: TPB=128, 4 cols/thread, lb(128,5), guard-free
//   interior strips (peeled warm-up + steady loop), 1 row per barrier,
//   2-buffer rotation. Block partial -> double atomic; last block finalizes.

#define BW   512
#define BH   512
#define NB   32
#define ROWS 23
#define TPB  128
#define STRIPS 23                    // 22 strips of 23 + one of 6
#define NBLOCKS (STRIPS * NB)        // 736
#define RVW  (BW / 4)                // float4s per row

__device__ double       g_acc;   // zero-init at load; reset by last block
__device__ unsigned int g_cnt;

__global__ __launch_bounds__(TPB, 5) void ncc_main_k(const float* __restrict__ gI,
                                                     const float* __restrict__ gJ,
                                                     float* __restrict__ out) {
    __shared__ float4 sV[2][5][TPB + 2];   // guard cols at 0 and TPB+1: 20.8KB
    __shared__ float  wsum[TPB / 32];

    const int t    = threadIdx.x;
    const int lane = t & 31;
    const int r0   = blockIdx.x * ROWS;
    const size_t img = (size_t)blockIdx.y * ((size_t)BH * BW);
    const float4 z = make_float4(0.f, 0.f, 0.f, 0.f);
    const float inv81 = 1.0f / 81.0f;

    const float4* bI = (const float4*)(gI + img) + t;   // stride RVW per row
    const float4* bJ = (const float4*)(gJ + img) + t;

    // One-time zero of the 20 guard entries (2 bufs x 5 products x 2 sides).
    // Ordered before any read by the barrier inside the first EMIT.
    if (t < 20) {
        const int b = t / 10, rem = t % 10, p = rem >> 1;
        sV[b][p][(rem & 1) ? (TPB + 1) : 0] = z;
    }

    float vI[4]  = {0.f, 0.f, 0.f, 0.f};
    float vJ[4]  = {0.f, 0.f, 0.f, 0.f};
    float vI2[4] = {0.f, 0.f, 0.f, 0.f};
    float vJ2[4] = {0.f, 0.f, 0.f, 0.f};
    float vIJ[4] = {0.f, 0.f, 0.f, 0.f};
    float acc = 0.f;

// Combined vertical running-sum update (R10 form).
#define VUPDATE(A1, B1, AO, BO)                                                \
    {                                                                          \
        const float an[4] = {(A1).x, (A1).y, (A1).z, (A1).w};                  \
        const float bn[4] = {(B1).x, (B1).y, (B1).z, (B1).w};                  \
        const float ap[4] = {(AO).x, (AO).y, (AO).z, (AO).w};                  \
        const float bp[4] = {(BO).x, (BO).y, (BO).z, (BO).w};                  \
        _Pragma("unroll")                                                      \
        for (int c = 0; c < 4; ++c) {                                          \
            vI[c] += an[c] - ap[c];                                            \
            vJ[c] += bn[c] - bp[c];                                            \
            vI2[c] = fmaf(an[c], an[c], fmaf(-ap[c], ap[c], vI2[c]));          \
            vJ2[c] = fmaf(bn[c], bn[c], fmaf(-bp[c], bp[c], vJ2[c]));          \
            vIJ[c] = fmaf(an[c], bn[c], fmaf(-ap[c], bp[c], vIJ[c]));          \
        }                                                                      \
    }

// 9-tap horizontal window for product P: 3 unconditional LDS.128 (guards).
#define DO_WIN(P)                                                              \
    {                                                                          \
        float4 L = sV[buf][P][t];                                              \
        float4 O = sV[buf][P][t + 1];                                          \
        float4 R = sV[buf][P][t + 2];                                          \
        float w = ((L.x + L.y) + (L.z + L.w))                                  \
                + ((O.x + O.y) + (O.z + O.w)) + R.x;                           \
        box[P][0] = w;                                                         \
        box[P][1] = w = w - L.x + R.y;                                         \
        box[P][2] = w = w - L.y + R.z;                                         \
        box[P][3] =     w - L.z + R.w;                                         \
    }

// Emit one output row via smem exchange buffer BUF (0/1).
#define EMIT(BUF)                                                              \
    {                                                                          \
        const int buf = (BUF);                                                 \
        sV[buf][0][t + 1] = make_float4(vI[0],  vI[1],  vI[2],  vI[3]);        \
        sV[buf][1][t + 1] = make_float4(vJ[0],  vJ[1],  vJ[2],  vJ[3]);        \
        sV[buf][2][t + 1] = make_float4(vI2[0], vI2[1], vI2[2], vI2[3]);       \
        sV[buf][3][t + 1] = make_float4(vJ2[0], vJ2[1], vJ2[2], vJ2[3]);       \
        sV[buf][4][t + 1] = make_float4(vIJ[0], vIJ[1], vIJ[2], vIJ[3]);       \
        __syncthreads();                                                       \
        float box[5][4];                                                       \
        DO_WIN(0)                                                              \
        DO_WIN(1)                                                              \
        DO_WIN(2)                                                              \
        DO_WIN(3)                                                              \
        DO_WIN(4)                                                              \
        _Pragma("unroll")                                                      \
        for (int c = 0; c < 4; ++c) {                                          \
            float sI = box[0][c], sJ = box[1][c];                              \
            float cross = fmaf(sI * sJ, -inv81, box[4][c]);                    \
            float Iv    = fmaf(sI * sI, -inv81, box[2][c]);                    \
            float Jv    = fmaf(sJ * sJ, -inv81, box[3][c]);                    \
            float den   = fmaf(Iv, Jv, 1e-5f);                                 \
            acc += __fdividef(cross * cross, den);                             \
        }                                                                      \
    }

    if (r0 >= ROWS && r0 + ROWS + 4 <= BH) {
        // ---------- interior strip (21 of 23): zero range checks ----------
        // Warm-up: add rows r0-4 .. r0+3 (all in-range), no subtract, no emit.
#pragma unroll
        for (int it = 0; it < 8; ++it) {
            const int rn = r0 - 4 + it;
            float4 a1 = __ldg(bI + (size_t)rn * RVW);
            float4 b1 = __ldg(bJ + (size_t)rn * RVW);
            float4 zo = z;
            VUPDATE(a1, b1, zo, zo)
        }
        {   // it = 8: window full, first emit, still no subtract.
            float4 a1 = __ldg(bI + (size_t)(r0 + 4) * RVW);
            float4 b1 = __ldg(bJ + (size_t)(r0 + 4) * RVW);
            float4 zo = z;
            VUPDATE(a1, b1, zo, zo)
            EMIT(0)
        }
        // Steady: it = 9..ROWS+7 — all loads/subtracts provably in-range.
#pragma unroll 2
        for (int it = 9; it < ROWS + 8; ++it) {
            const int rn = r0 - 4 + it;
            const int ro = rn - 9;
            float4 a1 = __ldg(bI + (size_t)rn * RVW);
            float4 b1 = __ldg(bJ + (size_t)rn * RVW);
            float4 ao = __ldg(bI + (size_t)ro * RVW);
            float4 bo = __ldg(bJ + (size_t)ro * RVW);
            VUPDATE(a1, b1, ao, bo)
            EMIT(it & 1)
        }
    } else {
        // ---------- edge strips: guarded generic loop (R10 verbatim) ----------
        const int rows_eff = min(ROWS, BH - r0);
        const int iters = rows_eff + 8;
#pragma unroll 2
        for (int it = 0; it < iters; ++it) {
            const int rn = r0 - 4 + it;
            const int ro = rn - 9;
            float4 a1 = z, b1 = z, ao = z, bo = z;
            if (rn >= 0 && rn < BH) {
                a1 = __ldg(bI + (size_t)rn * RVW);
                b1 = __ldg(bJ + (size_t)rn * RVW);
            }
            if (it >= 9 && ro >= 0) {   // only rows actually added earlier
                ao = __ldg(bI + (size_t)ro * RVW);
                bo = __ldg(bJ + (size_t)ro * RVW);
            }
            VUPDATE(a1, b1, ao, bo)
            if (it >= 8) EMIT(it & 1)
        }
    }
#undef DO_WIN
#undef EMIT
#undef VUPDATE

    // Block reduction -> global double atomic; last block finalizes + resets.
#pragma unroll
    for (int o = 16; o; o >>= 1) acc += __shfl_xor_sync(0xffffffffu, acc, o);
    if (lane == 0) wsum[t >> 5] = acc;
    __syncthreads();
    if (t == 0) {
        float bs = 0.f;
#pragma unroll
        for (int w = 0; w < TPB / 32; ++w) bs += wsum[w];
        atomicAdd(&g_acc, (double)bs);
        __threadfence();
        unsigned int done = atomicAdd(&g_cnt, 1u);
        if (done == NBLOCKS - 1) {
            __threadfence();
            double v = *((volatile double*)&g_acc);
            out[0] = (float)(-v * (1.0 / (double)((long long)NB * BH * BW)));
            g_acc = 0.0;          // reset for next graph replay
            g_cnt = 0u;
        }
    }
}

extern "C" void kernel_launch(void* const* d_in, const int* in_sizes, int n_in,
                              void* d_out, int out_size) {
    const float* I = (const float*)d_in[0];
    const float* J = (const float*)d_in[1];
    float* out = (float*)d_out;

    dim3 grid(STRIPS, NB);   // (23, 32) = 736 blocks, ~4.97/SM, single wave
    ncc_main_k<<<grid, TPB>>>(I, J, out);
}